// round 1
// baseline (speedup 1.0000x reference)
#include <cuda_runtime.h>
#include <math.h>

#define ENT   52
#define INNER 64
#define BB    8
#define SS    512
#define HH    768
#define NOUT  6656    /* ENT*2*INNER */
#define KDIM  1536
#define MDIM  4096    /* BB*SS */
#define BIGF  1000000000000.0f

// Scratch (device globals — no allocations allowed)
__device__ float g_cls_emb[BB * HH];                    // 24 KB
__device__ float g_qk[(long)BB * ENT * SS * 128];       // 109 MB: [b][e][s][c], c<64=q, c>=64=k

// ---------------------------------------------------------------------------
// Kernel 1: two GRU cells (fwd/bwd) on cls_pooled -> g_cls_emb[b][0:384 | 384:768]
// grid = 16 blocks (b*2+dir), 384 threads (one per hidden unit)
// ---------------------------------------------------------------------------
__global__ void gru_kernel(const float* __restrict__ cls, const float* __restrict__ h0,
                           const float* __restrict__ w_ih_f, const float* __restrict__ w_hh_f,
                           const float* __restrict__ b_ih_f, const float* __restrict__ b_hh_f,
                           const float* __restrict__ w_ih_b, const float* __restrict__ w_hh_b,
                           const float* __restrict__ b_ih_b, const float* __restrict__ b_hh_b)
{
    int dir = blockIdx.x & 1;
    int b   = blockIdx.x >> 1;
    int u   = threadIdx.x;                 // 0..383

    const float* w_ih = dir ? w_ih_b : w_ih_f;
    const float* w_hh = dir ? w_hh_b : w_hh_f;
    const float* b_ih = dir ? b_ih_b : b_ih_f;
    const float* b_hh = dir ? b_hh_b : b_hh_f;

    __shared__ float xs[HH];
    __shared__ float hs[384];
    for (int i = threadIdx.x; i < HH; i += blockDim.x) xs[i] = cls[b * HH + i];
    for (int i = threadIdx.x; i < 384; i += blockDim.x) hs[i] = h0[((long)dir * BB + b) * 384 + i];
    __syncthreads();

    float gi[3], gh[3];
#pragma unroll
    for (int g = 0; g < 3; g++) {
        const float* w = w_ih + (long)(g * 384 + u) * HH;
        float acc = b_ih[g * 384 + u];
#pragma unroll 4
        for (int k = 0; k < HH; k += 4) {
            float4 wv = *(const float4*)(w + k);
            acc += wv.x * xs[k] + wv.y * xs[k + 1] + wv.z * xs[k + 2] + wv.w * xs[k + 3];
        }
        gi[g] = acc;

        const float* w2 = w_hh + (long)(g * 384 + u) * 384;
        float acc2 = b_hh[g * 384 + u];
#pragma unroll 4
        for (int k = 0; k < 384; k += 4) {
            float4 wv = *(const float4*)(w2 + k);
            acc2 += wv.x * hs[k] + wv.y * hs[k + 1] + wv.z * hs[k + 2] + wv.w * hs[k + 3];
        }
        gh[g] = acc2;
    }

    float r = 1.0f / (1.0f + expf(-(gi[0] + gh[0])));
    float z = 1.0f / (1.0f + expf(-(gi[1] + gh[1])));
    float n = tanhf(gi[2] + r * gh[2]);
    float hnew = (1.0f - z) * n + z * hs[u];
    g_cls_emb[b * HH + dir * 384 + u] = hnew;
}

// ---------------------------------------------------------------------------
// Kernel 2: dense GEMM  C[m,n] = sum_k hidden[m,k] * dense_w[n,k] + dense_b[n]
//   hidden[m,k] = k<768 ? lhs[m*768+k] : cls_emb[b(m)*768 + k-768]
// Tiles: 128x128x16, 256 threads, 8x8 micro-tile. Writes into g_qk layout.
// grid = (52 entities = n-tiles, 32 m-tiles)
// ---------------------------------------------------------------------------
__global__ __launch_bounds__(256) void dense_kernel(const float* __restrict__ lhs,
                                                    const float* __restrict__ dw,
                                                    const float* __restrict__ db)
{
    __shared__ float As[16][128];
    __shared__ float Ws[16][128];

    int e  = blockIdx.x;        // entity = n-tile of 128
    int bm = blockIdx.y;        // m-tile
    int tid = threadIdx.x;
    int tx = tid & 15, ty = tid >> 4;

    int m0 = bm * 128;
    int n0 = e * 128;
    int bidx = m0 >> 9;         // batch index (all 128 rows in same batch: 512 % 128 == 0)

    int lr = tid >> 2;          // 0..63   (row within half-tile)
    int lc = (tid & 3) * 4;     // k offset 0,4,8,12

    float acc[8][8];
#pragma unroll
    for (int i = 0; i < 8; i++)
#pragma unroll
        for (int j = 0; j < 8; j++) acc[i][j] = 0.0f;

    for (int k0 = 0; k0 < KDIM; k0 += 16) {
#pragma unroll
        for (int half = 0; half < 2; half++) {
            int row = lr + half * 64;
            int k = k0 + lc;
            // A load (virtual concat)
            float4 v;
            if (k < HH) v = *(const float4*)(lhs + (long)(m0 + row) * HH + k);
            else        v = *(const float4*)(g_cls_emb + bidx * HH + (k - HH));
            As[lc + 0][row] = v.x; As[lc + 1][row] = v.y;
            As[lc + 2][row] = v.z; As[lc + 3][row] = v.w;
            // W load
            float4 w = *(const float4*)(dw + (long)(n0 + row) * KDIM + k);
            Ws[lc + 0][row] = w.x; Ws[lc + 1][row] = w.y;
            Ws[lc + 2][row] = w.z; Ws[lc + 3][row] = w.w;
        }
        __syncthreads();

#pragma unroll
        for (int kk = 0; kk < 16; kk++) {
            float a[8], wv[8];
#pragma unroll
            for (int i = 0; i < 8; i++) a[i] = As[kk][ty * 8 + i];
#pragma unroll
            for (int j = 0; j < 8; j++) wv[j] = Ws[kk][tx * 8 + j];
#pragma unroll
            for (int i = 0; i < 8; i++)
#pragma unroll
                for (int j = 0; j < 8; j++) acc[i][j] += a[i] * wv[j];
        }
        __syncthreads();
    }

    // Epilogue: add bias, write to g_qk[b][e][s][c]
    float bias[8];
#pragma unroll
    for (int j = 0; j < 8; j++) bias[j] = db[n0 + tx * 8 + j];

#pragma unroll
    for (int i = 0; i < 8; i++) {
        int s = (m0 + ty * 8 + i) & 511;
        long base = (((long)(bidx * ENT + e)) * SS + s) * 128 + tx * 8;
        float4 o0, o1;
        o0.x = acc[i][0] + bias[0]; o0.y = acc[i][1] + bias[1];
        o0.z = acc[i][2] + bias[2]; o0.w = acc[i][3] + bias[3];
        o1.x = acc[i][4] + bias[4]; o1.y = acc[i][5] + bias[5];
        o1.z = acc[i][6] + bias[6]; o1.w = acc[i][7] + bias[7];
        *(float4*)(g_qk + base)     = o0;
        *(float4*)(g_qk + base + 4) = o1;
    }
}

// ---------------------------------------------------------------------------
// Kernel 3: in-place RoPE on g_qk. One thread per (b,e,s,t) pair-group; each
// thread rotates one (even,odd) pair in q AND in k.
// ---------------------------------------------------------------------------
__global__ void rope_kernel()
{
    long idx = (long)blockIdx.x * blockDim.x + threadIdx.x;
    const long total = (long)BB * ENT * SS * 32;
    if (idx >= total) return;

    int t   = (int)(idx & 31);
    long row = idx >> 5;               // (b*52+e)*512 + s
    int s   = (int)(row & 511);

    float inv = powf(10000.0f, -(float)(2 * t) / 64.0f);
    float ang = (float)s * inv;
    float sn, cs;
    sincosf(ang, &sn, &cs);

    float* p = g_qk + row * 128 + 2 * t;
    float2 qv = *(float2*)p;
    float2 kv = *(float2*)(p + 64);
    float2 qo, ko;
    qo.x = qv.x * cs - qv.y * sn;  qo.y = qv.y * cs + qv.x * sn;
    ko.x = kv.x * cs - kv.y * sn;  ko.y = kv.y * cs + kv.x * sn;
    *(float2*)p        = qo;
    *(float2*)(p + 64) = ko;
}

// ---------------------------------------------------------------------------
// Kernel 4: logits[b,e,m,n] = (sum_d q[b,e,m,d]*k[b,e,n,d]) masked, /8
// 64x64 output tile per block (full K=64 in smem, d-major), 256 threads,
// 4x4 micro-tile. grid = (64 = 8 mt x 8 nt, 52, 8)
// ---------------------------------------------------------------------------
__global__ __launch_bounds__(256) void logits_kernel(const float* __restrict__ mask,
                                                     float* __restrict__ out)
{
    __shared__ float qs[64][68];   // [d][m], pad to 68 for alignment/banks
    __shared__ float ks[64][68];   // [d][n]

    int e = blockIdx.y;
    int b = blockIdx.z;
    int mt = blockIdx.x >> 3, nt = blockIdx.x & 7;
    int m0 = mt * 64, n0 = nt * 64;
    int tid = threadIdx.x;

    long rowbase = ((long)(b * ENT + e)) * SS;

    // Load q tile [m0..m0+63, d 0..63] and k tile [n0.., d 0..63], transposed to d-major
#pragma unroll
    for (int it = 0; it < 4; it++) {
        int li  = tid + it * 256;      // 0..1023
        int row = li >> 4;             // 0..63
        int dc  = (li & 15) * 4;       // 0..60
        float4 qv = *(const float4*)(g_qk + (rowbase + m0 + row) * 128 + dc);
        qs[dc + 0][row] = qv.x; qs[dc + 1][row] = qv.y;
        qs[dc + 2][row] = qv.z; qs[dc + 3][row] = qv.w;
        float4 kv = *(const float4*)(g_qk + (rowbase + n0 + row) * 128 + 64 + dc);
        ks[dc + 0][row] = kv.x; ks[dc + 1][row] = kv.y;
        ks[dc + 2][row] = kv.z; ks[dc + 3][row] = kv.w;
    }
    __syncthreads();

    int tx = tid & 15, ty = tid >> 4;
    float acc[4][4];
#pragma unroll
    for (int i = 0; i < 4; i++)
#pragma unroll
        for (int j = 0; j < 4; j++) acc[i][j] = 0.0f;

#pragma unroll
    for (int d = 0; d < 64; d++) {
        float4 qv = *(float4*)&qs[d][ty * 4];
        float4 kv = *(float4*)&ks[d][tx * 4];
        float qa[4] = {qv.x, qv.y, qv.z, qv.w};
        float ka[4] = {kv.x, kv.y, kv.z, kv.w};
#pragma unroll
        for (int i = 0; i < 4; i++)
#pragma unroll
            for (int j = 0; j < 4; j++) acc[i][j] += qa[i] * ka[j];
    }

    // Epilogue: mask + causal + scale, coalesced float4 stores
    float padv[4];
#pragma unroll
    for (int j = 0; j < 4; j++) padv[j] = mask[b * SS + n0 + tx * 4 + j];

#pragma unroll
    for (int i = 0; i < 4; i++) {
        int m = m0 + ty * 4 + i;
        float4 o;
        float v[4];
#pragma unroll
        for (int j = 0; j < 4; j++) {
            int n = n0 + tx * 4 + j;
            float x = acc[i][j] * padv[j] - (1.0f - padv[j]) * BIGF;
            if (m > n) x -= BIGF;
            v[j] = x * 0.125f;
        }
        o.x = v[0]; o.y = v[1]; o.z = v[2]; o.w = v[3];
        *(float4*)(out + (rowbase + m) * SS + n0 + tx * 4) = o;
    }
}

// ---------------------------------------------------------------------------
extern "C" void kernel_launch(void* const* d_in, const int* in_sizes, int n_in,
                              void* d_out, int out_size)
{
    const float* lhs    = (const float*)d_in[0];   // (8,512,768)
    const float* cls    = (const float*)d_in[1];   // (8,768)
    const float* h0     = (const float*)d_in[2];   // (2,8,384)
    const float* mask   = (const float*)d_in[3];   // (8,512)
    const float* w_ih_f = (const float*)d_in[4];
    const float* w_hh_f = (const float*)d_in[5];
    const float* b_ih_f = (const float*)d_in[6];
    const float* b_hh_f = (const float*)d_in[7];
    const float* w_ih_b = (const float*)d_in[8];
    const float* w_hh_b = (const float*)d_in[9];
    const float* b_ih_b = (const float*)d_in[10];
    const float* b_hh_b = (const float*)d_in[11];
    const float* dw     = (const float*)d_in[12];  // (6656,1536)
    const float* db     = (const float*)d_in[13];  // (6656,)
    float* out = (float*)d_out;                    // (8,52,512,512)

    gru_kernel<<<16, 384>>>(cls, h0, w_ih_f, w_hh_f, b_ih_f, b_hh_f,
                            w_ih_b, w_hh_b, b_ih_b, b_hh_b);

    dense_kernel<<<dim3(ENT, MDIM / 128), 256>>>(lhs, dw, db);

    const long rope_total = (long)BB * ENT * SS * 32;
    rope_kernel<<<(unsigned)((rope_total + 255) / 256), 256>>>();

    logits_kernel<<<dim3(64, ENT, BB), 256>>>(mask, out);
}

// round 3
// speedup vs baseline: 3.7474x; 3.7474x over previous
#include <cuda_runtime.h>
#include <cuda_bf16.h>
#include <math.h>
#include <stdint.h>

#define ENT   52
#define INNER 64
#define BB    8
#define SS    512
#define HH    768
#define NOUT  6656    /* ENT*2*INNER */
#define KDIM  1536
#define MDIM  4096    /* BB*SS */
#define BIGF  1000000000000.0f

// ---------------- scratch (device globals; no allocations allowed) ----------
__device__ float          g_cls_emb[BB * HH];                       // 24 KB
__device__ __nv_bfloat16  g_qk[(size_t)BB * ENT * SS * 128];        // 54.5 MB [b][e][s][c]
__device__ __nv_bfloat16  g_hidden[(size_t)MDIM * KDIM];            // 12.6 MB
__device__ __nv_bfloat16  g_wbf[(size_t)NOUT * KDIM];               // 20.4 MB
__device__ float2         g_rope[SS * 32];                          // 128 KB (cos,sin)

// ---------------- PTX helpers ----------------------------------------------
__device__ __forceinline__ uint32_t smem_u32(const void* p) {
    uint32_t a;
    asm("{ .reg .u64 t; cvta.to.shared.u64 t, %1; cvt.u32.u64 %0, t; }" : "=r"(a) : "l"(p));
    return a;
}
__device__ __forceinline__ void cp_async16(uint32_t dst, const void* src) {
    asm volatile("cp.async.cg.shared.global [%0], [%1], 16;\n" :: "r"(dst), "l"(src) : "memory");
}
__device__ __forceinline__ void cp_commit() {
    asm volatile("cp.async.commit_group;\n" ::: "memory");
}
__device__ __forceinline__ void ldsm4(uint32_t* r, uint32_t addr) {
    asm volatile("ldmatrix.sync.aligned.m8n8.x4.shared.b16 {%0,%1,%2,%3}, [%4];"
                 : "=r"(r[0]), "=r"(r[1]), "=r"(r[2]), "=r"(r[3]) : "r"(addr));
}
__device__ __forceinline__ void mma16816(float* c, const uint32_t* a, const uint32_t* b) {
    asm volatile(
        "mma.sync.aligned.m16n8k16.row.col.f32.bf16.bf16.f32 "
        "{%0,%1,%2,%3}, {%4,%5,%6,%7}, {%8,%9}, {%0,%1,%2,%3};"
        : "+f"(c[0]), "+f"(c[1]), "+f"(c[2]), "+f"(c[3])
        : "r"(a[0]), "r"(a[1]), "r"(a[2]), "r"(a[3]), "r"(b[0]), "r"(b[1]));
}

// ---------------------------------------------------------------------------
// Kernel 1: GRU cells (validated in round 1)
// ---------------------------------------------------------------------------
__global__ void gru_kernel(const float* __restrict__ cls, const float* __restrict__ h0,
                           const float* __restrict__ w_ih_f, const float* __restrict__ w_hh_f,
                           const float* __restrict__ b_ih_f, const float* __restrict__ b_hh_f,
                           const float* __restrict__ w_ih_b, const float* __restrict__ w_hh_b,
                           const float* __restrict__ b_ih_b, const float* __restrict__ b_hh_b)
{
    int dir = blockIdx.x & 1;
    int b   = blockIdx.x >> 1;
    int u   = threadIdx.x;

    const float* w_ih = dir ? w_ih_b : w_ih_f;
    const float* w_hh = dir ? w_hh_b : w_hh_f;
    const float* b_ih = dir ? b_ih_b : b_ih_f;
    const float* b_hh = dir ? b_hh_b : b_hh_f;

    __shared__ float xs[HH];
    __shared__ float hs[384];
    for (int i = threadIdx.x; i < HH; i += blockDim.x) xs[i] = cls[b * HH + i];
    for (int i = threadIdx.x; i < 384; i += blockDim.x) hs[i] = h0[((long)dir * BB + b) * 384 + i];
    __syncthreads();

    float gi[3], gh[3];
#pragma unroll
    for (int g = 0; g < 3; g++) {
        const float* w = w_ih + (long)(g * 384 + u) * HH;
        float acc = b_ih[g * 384 + u];
#pragma unroll 4
        for (int k = 0; k < HH; k += 4) {
            float4 wv = *(const float4*)(w + k);
            acc += wv.x * xs[k] + wv.y * xs[k + 1] + wv.z * xs[k + 2] + wv.w * xs[k + 3];
        }
        gi[g] = acc;
        const float* w2 = w_hh + (long)(g * 384 + u) * 384;
        float acc2 = b_hh[g * 384 + u];
#pragma unroll 4
        for (int k = 0; k < 384; k += 4) {
            float4 wv = *(const float4*)(w2 + k);
            acc2 += wv.x * hs[k] + wv.y * hs[k + 1] + wv.z * hs[k + 2] + wv.w * hs[k + 3];
        }
        gh[g] = acc2;
    }
    float r = 1.0f / (1.0f + expf(-(gi[0] + gh[0])));
    float z = 1.0f / (1.0f + expf(-(gi[1] + gh[1])));
    float n = tanhf(gi[2] + r * gh[2]);
    g_cls_emb[b * HH + dir * 384 + u] = (1.0f - z) * n + z * hs[u];
}

// ---------------------------------------------------------------------------
// Kernel 1b: weights fp32 -> bf16
// ---------------------------------------------------------------------------
__global__ void conv_w_kernel(const float* __restrict__ dw)
{
    size_t i = ((size_t)blockIdx.x * blockDim.x + threadIdx.x) * 4;
    float4 v = *(const float4*)(dw + i);
    __nv_bfloat162 p0 = __floats2bfloat162_rn(v.x, v.y);
    __nv_bfloat162 p1 = __floats2bfloat162_rn(v.z, v.w);
    uint2 o; o.x = *(uint32_t*)&p0; o.y = *(uint32_t*)&p1;
    *(uint2*)(g_wbf + i) = o;
}

// ---------------------------------------------------------------------------
// Kernel 1c: hidden bf16 = concat(lhs, cls_emb broadcast)
// ---------------------------------------------------------------------------
__global__ void build_hidden_kernel(const float* __restrict__ lhs)
{
    size_t gid = (size_t)blockIdx.x * blockDim.x + threadIdx.x;
    int m  = (int)(gid / 384);
    int kq = (int)(gid % 384) * 4;
    float4 v;
    if (kq < HH) v = *(const float4*)(lhs + (size_t)m * HH + kq);
    else         v = *(const float4*)(g_cls_emb + (m >> 9) * HH + (kq - HH));
    __nv_bfloat162 p0 = __floats2bfloat162_rn(v.x, v.y);
    __nv_bfloat162 p1 = __floats2bfloat162_rn(v.z, v.w);
    uint2 o; o.x = *(uint32_t*)&p0; o.y = *(uint32_t*)&p1;
    *(uint2*)(g_hidden + (size_t)m * KDIM + kq) = o;
}

// ---------------------------------------------------------------------------
// Kernel 1d: RoPE sin/cos table (accurate sincosf, once)
// ---------------------------------------------------------------------------
__global__ void rope_tab_kernel()
{
    int idx = blockIdx.x * blockDim.x + threadIdx.x;   // 0..16383
    int s = idx >> 5, t = idx & 31;
    float invf = powf(10000.0f, -2.0f * (float)t / 64.0f);
    float sn, cs;
    sincosf((float)s * invf, &sn, &cs);
    g_rope[idx] = make_float2(cs, sn);
}

// ---------------------------------------------------------------------------
// Kernel 2: dense GEMM via mma.sync bf16. CTA 128x128x32, 8 warps (2Mx4N),
// warp tile 64x32, 4-stage cp.async. Epilogue: bias + RoPE -> bf16 g_qk.
// grid (52, 32), 256 threads.
// ---------------------------------------------------------------------------
#define AROWB 80                      /* 32 bf16 + 8 pad = 80 bytes/row */
#define STGB  (128 * AROWB)           /* 10240 per operand per stage */
#define DSMEM_DENSE (8 * STGB)        /* 4 stages x (A+B) = 81920 */

__global__ __launch_bounds__(256, 2) void dense_mma_kernel(const float* __restrict__ db)
{
    extern __shared__ char dsm[];
    const uint32_t sA = smem_u32(dsm);
    const uint32_t sB = sA + 4 * STGB;
    __shared__ float bias_s[128];

    const int e  = blockIdx.x;
    const int mt = blockIdx.y;
    const int m0 = mt * 128;
    const int n0 = e * 128;
    const int tid = threadIdx.x;
    const int lane = tid & 31;
    const int wid  = tid >> 5;
    const int warpM = wid >> 2;       // 0..1
    const int warpN = wid & 3;        // 0..3

    if (tid < 128) bias_s[tid] = db[n0 + tid];

    const __nv_bfloat16* gA = g_hidden + (size_t)m0 * KDIM;
    const __nv_bfloat16* gB = g_wbf    + (size_t)n0 * KDIM;

    auto load_chunk = [&](int st, int ck) {
        const __nv_bfloat16* ga = gA + ck * 32;
        const __nv_bfloat16* gb = gB + ck * 32;
#pragma unroll
        for (int i = 0; i < 2; i++) {
            int id  = tid * 2 + i;          // 0..511
            int row = id >> 2, seg = id & 3;
            uint32_t off = (uint32_t)(st * STGB + row * AROWB + seg * 16);
            cp_async16(sA + off, ga + (size_t)row * KDIM + seg * 8);
            cp_async16(sB + off, gb + (size_t)row * KDIM + seg * 8);
        }
        cp_commit();
    };

    float acc[4][4][4];
#pragma unroll
    for (int i = 0; i < 4; i++)
#pragma unroll
        for (int j = 0; j < 4; j++)
#pragma unroll
            for (int r = 0; r < 4; r++) acc[i][j][r] = 0.0f;

#pragma unroll
    for (int s = 0; s < 3; s++) load_chunk(s, s);

    const int NCH = KDIM / 32;   // 48
    for (int k = 0; k < NCH; k++) {
        int st = k & 3;
        asm volatile("cp.async.wait_group 2;\n" ::: "memory");
        __syncthreads();
        if (k + 3 < NCH) load_chunk((k + 3) & 3, k + 3);
        else             cp_commit();          // keep group accounting aligned

        uint32_t aS = sA + st * STGB;
        uint32_t bS = sB + st * STGB;
#pragma unroll
        for (int kstep = 0; kstep < 2; kstep++) {
            uint32_t areg[4][4], breg[4][2];
#pragma unroll
            for (int mi = 0; mi < 4; mi++)
                ldsm4(areg[mi], aS + (uint32_t)((warpM * 64 + mi * 16 + (lane & 15)) * AROWB
                                                + kstep * 32 + (lane >> 4) * 16));
#pragma unroll
            for (int jp = 0; jp < 2; jp++) {
                uint32_t t4[4];
                ldsm4(t4, bS + (uint32_t)((warpN * 32 + jp * 16 + (lane & 15)) * AROWB
                                          + kstep * 32 + (lane >> 4) * 16));
                breg[jp * 2][0]     = t4[0];
                breg[jp * 2 + 1][0] = t4[1];
                breg[jp * 2][1]     = t4[2];
                breg[jp * 2 + 1][1] = t4[3];
            }
#pragma unroll
            for (int mi = 0; mi < 4; mi++)
#pragma unroll
                for (int j = 0; j < 4; j++)
                    mma16816(acc[mi][j], areg[mi], breg[j]);
        }
    }

    // ---- epilogue: bias + RoPE, bf16 store ---------------------------------
    const int g = lane >> 2, q = lane & 3;
#pragma unroll
    for (int mi = 0; mi < 4; mi++) {
#pragma unroll
        for (int h = 0; h < 2; h++) {
            int m = m0 + warpM * 64 + mi * 16 + h * 8 + g;
            int s = m & 511;
            int bsel = m >> 9;
            size_t obase = (((size_t)(bsel * ENT + e)) * SS + s) * 128;
#pragma unroll
            for (int j = 0; j < 4; j++) {
                int c = warpN * 32 + j * 8 + 2 * q;     // even col, 0..126
                float x = acc[mi][j][h * 2]     + bias_s[c];
                float y = acc[mi][j][h * 2 + 1] + bias_s[c + 1];
                int t = (c & 63) >> 1;
                float2 rc = g_rope[s * 32 + t];
                float rx = x * rc.x - y * rc.y;
                float ry = y * rc.x + x * rc.y;
                __nv_bfloat162 p = __floats2bfloat162_rn(rx, ry);
                *(uint32_t*)(g_qk + obase + c) = *(uint32_t*)&p;
            }
        }
    }
}

// ---------------------------------------------------------------------------
// Kernel 3: logits via mma.sync bf16. CTA 128x128, K=64 in smem.
// grid (16, 52, 8), 256 threads.
// ---------------------------------------------------------------------------
#define QROWB 144                      /* 64 bf16 + 8 pad = 144 bytes/row */
#define DSMEM_LOG (2 * 128 * QROWB)    /* 36864 */

__global__ __launch_bounds__(256) void logits_kernel(const float* __restrict__ mask,
                                                     float* __restrict__ out)
{
    extern __shared__ char lsm[];
    const uint32_t sQ = smem_u32(lsm);
    const uint32_t sK = sQ + 128 * QROWB;

    const int e = blockIdx.y;
    const int b = blockIdx.z;
    const int mt = blockIdx.x >> 2, nt = blockIdx.x & 3;
    const int m0 = mt * 128, n0 = nt * 128;
    const int tid = threadIdx.x;
    const int lane = tid & 31;
    const int wid  = tid >> 5;
    const int warpM = wid >> 2;       // 0..1
    const int warpN = wid & 3;        // 0..3

    const size_t rowbase = ((size_t)(b * ENT + e)) * SS;

    // load Q (cols 0-63) and K (cols 64-127) tiles, 8 segs/row each
#pragma unroll
    for (int i = 0; i < 4; i++) {
        int id  = tid * 4 + i;          // 0..1023
        int row = id >> 3, seg = id & 7;
        uint32_t off = (uint32_t)(row * QROWB + seg * 16);
        cp_async16(sQ + off, g_qk + (rowbase + m0 + row) * 128 + seg * 8);
        cp_async16(sK + off, g_qk + (rowbase + n0 + row) * 128 + 64 + seg * 8);
    }
    cp_commit();
    asm volatile("cp.async.wait_group 0;\n" ::: "memory");
    __syncthreads();

    float acc[4][4][4];
#pragma unroll
    for (int i = 0; i < 4; i++)
#pragma unroll
        for (int j = 0; j < 4; j++)
#pragma unroll
            for (int r = 0; r < 4; r++) acc[i][j][r] = 0.0f;

#pragma unroll
    for (int kstep = 0; kstep < 4; kstep++) {
        uint32_t areg[4][4], breg[4][2];
#pragma unroll
        for (int mi = 0; mi < 4; mi++)
            ldsm4(areg[mi], sQ + (uint32_t)((warpM * 64 + mi * 16 + (lane & 15)) * QROWB
                                            + kstep * 32 + (lane >> 4) * 16));
#pragma unroll
        for (int jp = 0; jp < 2; jp++) {
            uint32_t t4[4];
            ldsm4(t4, sK + (uint32_t)((warpN * 32 + jp * 16 + (lane & 15)) * QROWB
                                      + kstep * 32 + (lane >> 4) * 16));
            breg[jp * 2][0]     = t4[0];
            breg[jp * 2 + 1][0] = t4[1];
            breg[jp * 2][1]     = t4[2];
            breg[jp * 2 + 1][1] = t4[3];
        }
#pragma unroll
        for (int mi = 0; mi < 4; mi++)
#pragma unroll
            for (int j = 0; j < 4; j++)
                mma16816(acc[mi][j], areg[mi], breg[j]);
    }

    // ---- epilogue: mask + causal + scale, float2 stores --------------------
    const int g = lane >> 2, q = lane & 3;
    const int nbase = n0 + warpN * 32;
    float p0[4], p1[4];
#pragma unroll
    for (int j = 0; j < 4; j++) {
        int c = nbase + j * 8 + 2 * q;
        p0[j] = mask[b * SS + c];
        p1[j] = mask[b * SS + c + 1];
    }

#pragma unroll
    for (int mi = 0; mi < 4; mi++) {
#pragma unroll
        for (int h = 0; h < 2; h++) {
            int m = m0 + warpM * 64 + mi * 16 + h * 8 + g;
            size_t orow = (rowbase + m) * SS;
#pragma unroll
            for (int j = 0; j < 4; j++) {
                int c = nbase + j * 8 + 2 * q;
                float x = acc[mi][j][h * 2];
                float y = acc[mi][j][h * 2 + 1];
                x = x * p0[j] - (1.0f - p0[j]) * BIGF;
                y = y * p1[j] - (1.0f - p1[j]) * BIGF;
                if (m > c)     x -= BIGF;
                if (m > c + 1) y -= BIGF;
                *(float2*)(out + orow + c) = make_float2(x * 0.125f, y * 0.125f);
            }
        }
    }
}

// ---------------------------------------------------------------------------
extern "C" void kernel_launch(void* const* d_in, const int* in_sizes, int n_in,
                              void* d_out, int out_size)
{
    const float* lhs    = (const float*)d_in[0];
    const float* cls    = (const float*)d_in[1];
    const float* h0     = (const float*)d_in[2];
    const float* mask   = (const float*)d_in[3];
    const float* w_ih_f = (const float*)d_in[4];
    const float* w_hh_f = (const float*)d_in[5];
    const float* b_ih_f = (const float*)d_in[6];
    const float* b_hh_f = (const float*)d_in[7];
    const float* w_ih_b = (const float*)d_in[8];
    const float* w_hh_b = (const float*)d_in[9];
    const float* b_ih_b = (const float*)d_in[10];
    const float* b_hh_b = (const float*)d_in[11];
    const float* dw     = (const float*)d_in[12];
    const float* db     = (const float*)d_in[13];
    float* out = (float*)d_out;

    cudaFuncSetAttribute(dense_mma_kernel, cudaFuncAttributeMaxDynamicSharedMemorySize, DSMEM_DENSE);
    cudaFuncSetAttribute(logits_kernel,    cudaFuncAttributeMaxDynamicSharedMemorySize, DSMEM_LOG);

    rope_tab_kernel<<<64, 256>>>();
    conv_w_kernel<<<(NOUT * KDIM / 4) / 256, 256>>>(dw);
    gru_kernel<<<16, 384>>>(cls, h0, w_ih_f, w_hh_f, b_ih_f, b_hh_f,
                            w_ih_b, w_hh_b, b_ih_b, b_hh_b);
    build_hidden_kernel<<<(MDIM * KDIM / 4) / 256, 256>>>(lhs);

    dense_mma_kernel<<<dim3(ENT, MDIM / 128), 256, DSMEM_DENSE>>>(db);

    logits_kernel<<<dim3(16, ENT, BB), 256, DSMEM_LOG>>>(mask, out);
}

// round 4
// speedup vs baseline: 4.3380x; 1.1576x over previous
#include <cuda_runtime.h>
#include <cuda_bf16.h>
#include <math.h>
#include <stdint.h>

#define ENT   52
#define INNER 64
#define BB    8
#define SS    512
#define HH    768
#define NOUT  6656    /* ENT*2*INNER */
#define KDIM  1536
#define MDIM  4096    /* BB*SS */
#define BIGF  1000000000000.0f

// ---------------- scratch (device globals; no allocations allowed) ----------
__device__ float          g_cls_emb[BB * HH];                       // 24 KB
__device__ __nv_bfloat16  g_qk[(size_t)BB * ENT * SS * 128];        // 54.5 MB [b][e][s][c]
__device__ __nv_bfloat16  g_hidden[(size_t)MDIM * KDIM];            // 12.6 MB
__device__ __nv_bfloat16  g_wbf[(size_t)NOUT * KDIM];               // 20.4 MB
__device__ float2         g_rope[SS * 32];                          // 128 KB (cos,sin)

// ---------------- PTX helpers ----------------------------------------------
__device__ __forceinline__ uint32_t smem_u32(const void* p) {
    uint32_t a;
    asm("{ .reg .u64 t; cvta.to.shared.u64 t, %1; cvt.u32.u64 %0, t; }" : "=r"(a) : "l"(p));
    return a;
}
__device__ __forceinline__ void cp_async16(uint32_t dst, const void* src) {
    asm volatile("cp.async.cg.shared.global [%0], [%1], 16;\n" :: "r"(dst), "l"(src) : "memory");
}
__device__ __forceinline__ void cp_commit() {
    asm volatile("cp.async.commit_group;\n" ::: "memory");
}
__device__ __forceinline__ void ldsm4(uint32_t* r, uint32_t addr) {
    asm volatile("ldmatrix.sync.aligned.m8n8.x4.shared.b16 {%0,%1,%2,%3}, [%4];"
                 : "=r"(r[0]), "=r"(r[1]), "=r"(r[2]), "=r"(r[3]) : "r"(addr));
}
__device__ __forceinline__ void mma16816(float* c, const uint32_t* a, const uint32_t* b) {
    asm volatile(
        "mma.sync.aligned.m16n8k16.row.col.f32.bf16.bf16.f32 "
        "{%0,%1,%2,%3}, {%4,%5,%6,%7}, {%8,%9}, {%0,%1,%2,%3};"
        : "+f"(c[0]), "+f"(c[1]), "+f"(c[2]), "+f"(c[3])
        : "r"(a[0]), "r"(a[1]), "r"(a[2]), "r"(a[3]), "r"(b[0]), "r"(b[1]));
}

// ---------------------------------------------------------------------------
// Kernel 1: GRU cells — weight-broadcast layout.
// grid (12 uchunks, 2 dirs), 256 threads = 32 units x 8 batches.
// ---------------------------------------------------------------------------
__global__ __launch_bounds__(256) void gru_kernel(
    const float* __restrict__ cls, const float* __restrict__ h0,
    const float* __restrict__ w_ih_f, const float* __restrict__ w_hh_f,
    const float* __restrict__ b_ih_f, const float* __restrict__ b_hh_f,
    const float* __restrict__ w_ih_b, const float* __restrict__ w_hh_b,
    const float* __restrict__ b_ih_b, const float* __restrict__ b_hh_b)
{
    const int dir = blockIdx.y;
    const int u   = blockIdx.x * 32 + (threadIdx.x >> 3);  // unit 0..383
    const int b   = threadIdx.x & 7;

    const float* w_ih = dir ? w_ih_b : w_ih_f;
    const float* w_hh = dir ? w_hh_b : w_hh_f;
    const float* b_ih = dir ? b_ih_b : b_ih_f;
    const float* b_hh = dir ? b_hh_b : b_hh_f;

    __shared__ float xs[BB][HH + 4];    // pitch 772 -> conflict-free
    __shared__ float hs[BB][384 + 4];   // pitch 388

    for (int i = threadIdx.x; i < BB * HH; i += blockDim.x)
        xs[i / HH][i % HH] = cls[i];
    for (int i = threadIdx.x; i < BB * 384; i += blockDim.x)
        hs[i / 384][i % 384] = h0[(size_t)dir * BB * 384 + i];
    __syncthreads();

    float gi[3], gh[3];
#pragma unroll
    for (int g = 0; g < 3; g++) {
        const float* w = w_ih + (size_t)(g * 384 + u) * HH;
        float acc = b_ih[g * 384 + u];
#pragma unroll 4
        for (int k = 0; k < HH; k += 4) {
            float4 wv = *(const float4*)(w + k);
            acc += wv.x * xs[b][k] + wv.y * xs[b][k + 1] + wv.z * xs[b][k + 2] + wv.w * xs[b][k + 3];
        }
        gi[g] = acc;
        const float* w2 = w_hh + (size_t)(g * 384 + u) * 384;
        float acc2 = b_hh[g * 384 + u];
#pragma unroll 4
        for (int k = 0; k < 384; k += 4) {
            float4 wv = *(const float4*)(w2 + k);
            acc2 += wv.x * hs[b][k] + wv.y * hs[b][k + 1] + wv.z * hs[b][k + 2] + wv.w * hs[b][k + 3];
        }
        gh[g] = acc2;
    }
    float r = 1.0f / (1.0f + expf(-(gi[0] + gh[0])));
    float z = 1.0f / (1.0f + expf(-(gi[1] + gh[1])));
    float n = tanhf(gi[2] + r * gh[2]);
    g_cls_emb[b * HH + dir * 384 + u] = (1.0f - z) * n + z * hs[b][u];
}

// ---------------------------------------------------------------------------
// Kernel 1b: weights fp32 -> bf16
// ---------------------------------------------------------------------------
__global__ void conv_w_kernel(const float* __restrict__ dw)
{
    size_t i = ((size_t)blockIdx.x * blockDim.x + threadIdx.x) * 4;
    float4 v = *(const float4*)(dw + i);
    __nv_bfloat162 p0 = __floats2bfloat162_rn(v.x, v.y);
    __nv_bfloat162 p1 = __floats2bfloat162_rn(v.z, v.w);
    uint2 o; o.x = *(uint32_t*)&p0; o.y = *(uint32_t*)&p1;
    *(uint2*)(g_wbf + i) = o;
}

// ---------------------------------------------------------------------------
// Kernel 1c: hidden bf16 = concat(lhs, cls_emb broadcast)
// ---------------------------------------------------------------------------
__global__ void build_hidden_kernel(const float* __restrict__ lhs)
{
    size_t gid = (size_t)blockIdx.x * blockDim.x + threadIdx.x;
    int m  = (int)(gid / 384);
    int kq = (int)(gid % 384) * 4;
    float4 v;
    if (kq < HH) v = *(const float4*)(lhs + (size_t)m * HH + kq);
    else         v = *(const float4*)(g_cls_emb + (m >> 9) * HH + (kq - HH));
    __nv_bfloat162 p0 = __floats2bfloat162_rn(v.x, v.y);
    __nv_bfloat162 p1 = __floats2bfloat162_rn(v.z, v.w);
    uint2 o; o.x = *(uint32_t*)&p0; o.y = *(uint32_t*)&p1;
    *(uint2*)(g_hidden + (size_t)m * KDIM + kq) = o;
}

// ---------------------------------------------------------------------------
// Kernel 1d: RoPE sin/cos table
// ---------------------------------------------------------------------------
__global__ void rope_tab_kernel()
{
    int idx = blockIdx.x * blockDim.x + threadIdx.x;   // 0..16383
    int s = idx >> 5, t = idx & 31;
    float invf = powf(10000.0f, -2.0f * (float)t / 64.0f);
    float sn, cs;
    sincosf((float)s * invf, &sn, &cs);
    g_rope[idx] = make_float2(cs, sn);
}

// ---------------------------------------------------------------------------
// Kernel 2: dense GEMM via mma.sync bf16 (validated round 3, unchanged).
// ---------------------------------------------------------------------------
#define AROWB 80
#define STGB  (128 * AROWB)
#define DSMEM_DENSE (8 * STGB)

__global__ __launch_bounds__(256, 2) void dense_mma_kernel(const float* __restrict__ db)
{
    extern __shared__ char dsm[];
    const uint32_t sA = smem_u32(dsm);
    const uint32_t sB = sA + 4 * STGB;
    __shared__ float bias_s[128];

    const int e  = blockIdx.x;
    const int mt = blockIdx.y;
    const int m0 = mt * 128;
    const int n0 = e * 128;
    const int tid = threadIdx.x;
    const int lane = tid & 31;
    const int wid  = tid >> 5;
    const int warpM = wid >> 2;
    const int warpN = wid & 3;

    if (tid < 128) bias_s[tid] = db[n0 + tid];

    const __nv_bfloat16* gA = g_hidden + (size_t)m0 * KDIM;
    const __nv_bfloat16* gB = g_wbf    + (size_t)n0 * KDIM;

    auto load_chunk = [&](int st, int ck) {
        const __nv_bfloat16* ga = gA + ck * 32;
        const __nv_bfloat16* gb = gB + ck * 32;
#pragma unroll
        for (int i = 0; i < 2; i++) {
            int id  = tid * 2 + i;
            int row = id >> 2, seg = id & 3;
            uint32_t off = (uint32_t)(st * STGB + row * AROWB + seg * 16);
            cp_async16(sA + off, ga + (size_t)row * KDIM + seg * 8);
            cp_async16(sB + off, gb + (size_t)row * KDIM + seg * 8);
        }
        cp_commit();
    };

    float acc[4][4][4];
#pragma unroll
    for (int i = 0; i < 4; i++)
#pragma unroll
        for (int j = 0; j < 4; j++)
#pragma unroll
            for (int r = 0; r < 4; r++) acc[i][j][r] = 0.0f;

#pragma unroll
    for (int s = 0; s < 3; s++) load_chunk(s, s);

    const int NCH = KDIM / 32;
    for (int k = 0; k < NCH; k++) {
        int st = k & 3;
        asm volatile("cp.async.wait_group 2;\n" ::: "memory");
        __syncthreads();
        if (k + 3 < NCH) load_chunk((k + 3) & 3, k + 3);
        else             cp_commit();

        uint32_t aS = sA + st * STGB;
        uint32_t bS = sB + st * STGB;
#pragma unroll
        for (int kstep = 0; kstep < 2; kstep++) {
            uint32_t areg[4][4], breg[4][2];
#pragma unroll
            for (int mi = 0; mi < 4; mi++)
                ldsm4(areg[mi], aS + (uint32_t)((warpM * 64 + mi * 16 + (lane & 15)) * AROWB
                                                + kstep * 32 + (lane >> 4) * 16));
#pragma unroll
            for (int jp = 0; jp < 2; jp++) {
                uint32_t t4[4];
                ldsm4(t4, bS + (uint32_t)((warpN * 32 + jp * 16 + (lane & 15)) * AROWB
                                          + kstep * 32 + (lane >> 4) * 16));
                breg[jp * 2][0]     = t4[0];
                breg[jp * 2 + 1][0] = t4[1];
                breg[jp * 2][1]     = t4[2];
                breg[jp * 2 + 1][1] = t4[3];
            }
#pragma unroll
            for (int mi = 0; mi < 4; mi++)
#pragma unroll
                for (int j = 0; j < 4; j++)
                    mma16816(acc[mi][j], areg[mi], breg[j]);
        }
    }

    const int g = lane >> 2, q = lane & 3;
#pragma unroll
    for (int mi = 0; mi < 4; mi++) {
#pragma unroll
        for (int h = 0; h < 2; h++) {
            int m = m0 + warpM * 64 + mi * 16 + h * 8 + g;
            int s = m & 511;
            int bsel = m >> 9;
            size_t obase = (((size_t)(bsel * ENT + e)) * SS + s) * 128;
#pragma unroll
            for (int j = 0; j < 4; j++) {
                int c = warpN * 32 + j * 8 + 2 * q;
                float x = acc[mi][j][h * 2]     + bias_s[c];
                float y = acc[mi][j][h * 2 + 1] + bias_s[c + 1];
                int t = (c & 63) >> 1;
                float2 rc = g_rope[s * 32 + t];
                float rx = x * rc.x - y * rc.y;
                float ry = y * rc.x + x * rc.y;
                __nv_bfloat162 p = __floats2bfloat162_rn(rx, ry);
                *(uint32_t*)(g_qk + obase + c) = *(uint32_t*)&p;
            }
        }
    }
}

// ---------------------------------------------------------------------------
// Kernel 3: logits via mma.sync bf16 + causal-tile skip + streaming stores.
// grid (16, 52, 8), 256 threads.
// ---------------------------------------------------------------------------
#define QROWB 144
#define DSMEM_LOG (2 * 128 * QROWB)

__global__ __launch_bounds__(256) void logits_kernel(const float* __restrict__ mask,
                                                     float* __restrict__ out)
{
    extern __shared__ char lsm[];
    const uint32_t sQ = smem_u32(lsm);
    const uint32_t sK = sQ + 128 * QROWB;

    const int e = blockIdx.y;
    const int b = blockIdx.z;
    const int mt = blockIdx.x >> 2, nt = blockIdx.x & 3;
    const int m0 = mt * 128, n0 = nt * 128;
    const int tid = threadIdx.x;

    const size_t rowbase = ((size_t)(b * ENT + e)) * SS;

    // ---- fully-causal tile: all m > n. acc contribution is ~2e-11 of the
    // output norm — write the masked constant directly, skip loads + MMA. ----
    if (mt > nt) {
        int cg = (tid & 31) * 4;
        float4 v;
        {
            float p0 = mask[b * SS + n0 + cg];
            float p1 = mask[b * SS + n0 + cg + 1];
            float p2 = mask[b * SS + n0 + cg + 2];
            float p3 = mask[b * SS + n0 + cg + 3];
            v = make_float4(((p0 - 1.0f) * BIGF - BIGF) * 0.125f,
                            ((p1 - 1.0f) * BIGF - BIGF) * 0.125f,
                            ((p2 - 1.0f) * BIGF - BIGF) * 0.125f,
                            ((p3 - 1.0f) * BIGF - BIGF) * 0.125f);
        }
        for (int r = tid >> 5; r < 128; r += 8)
            __stcs((float4*)(out + (rowbase + m0 + r) * SS + n0 + cg), v);
        return;
    }

    const int lane = tid & 31;
    const int wid  = tid >> 5;
    const int warpM = wid >> 2;
    const int warpN = wid & 3;

#pragma unroll
    for (int i = 0; i < 4; i++) {
        int id  = tid * 4 + i;
        int row = id >> 3, seg = id & 7;
        uint32_t off = (uint32_t)(row * QROWB + seg * 16);
        cp_async16(sQ + off, g_qk + (rowbase + m0 + row) * 128 + seg * 8);
        cp_async16(sK + off, g_qk + (rowbase + n0 + row) * 128 + 64 + seg * 8);
    }
    cp_commit();
    asm volatile("cp.async.wait_group 0;\n" ::: "memory");
    __syncthreads();

    float acc[4][4][4];
#pragma unroll
    for (int i = 0; i < 4; i++)
#pragma unroll
        for (int j = 0; j < 4; j++)
#pragma unroll
            for (int r = 0; r < 4; r++) acc[i][j][r] = 0.0f;

#pragma unroll
    for (int kstep = 0; kstep < 4; kstep++) {
        uint32_t areg[4][4], breg[4][2];
#pragma unroll
        for (int mi = 0; mi < 4; mi++)
            ldsm4(areg[mi], sQ + (uint32_t)((warpM * 64 + mi * 16 + (lane & 15)) * QROWB
                                            + kstep * 32 + (lane >> 4) * 16));
#pragma unroll
        for (int jp = 0; jp < 2; jp++) {
            uint32_t t4[4];
            ldsm4(t4, sK + (uint32_t)((warpN * 32 + jp * 16 + (lane & 15)) * QROWB
                                      + kstep * 32 + (lane >> 4) * 16));
            breg[jp * 2][0]     = t4[0];
            breg[jp * 2 + 1][0] = t4[1];
            breg[jp * 2][1]     = t4[2];
            breg[jp * 2 + 1][1] = t4[3];
        }
#pragma unroll
        for (int mi = 0; mi < 4; mi++)
#pragma unroll
            for (int j = 0; j < 4; j++)
                mma16816(acc[mi][j], areg[mi], breg[j]);
    }

    const int g = lane >> 2, q = lane & 3;
    const int nbase = n0 + warpN * 32;
    float p0[4], p1[4];
#pragma unroll
    for (int j = 0; j < 4; j++) {
        int c = nbase + j * 8 + 2 * q;
        p0[j] = mask[b * SS + c];
        p1[j] = mask[b * SS + c + 1];
    }

#pragma unroll
    for (int mi = 0; mi < 4; mi++) {
#pragma unroll
        for (int h = 0; h < 2; h++) {
            int m = m0 + warpM * 64 + mi * 16 + h * 8 + g;
            size_t orow = (rowbase + m) * SS;
#pragma unroll
            for (int j = 0; j < 4; j++) {
                int c = nbase + j * 8 + 2 * q;
                float x = acc[mi][j][h * 2];
                float y = acc[mi][j][h * 2 + 1];
                x = x * p0[j] - (1.0f - p0[j]) * BIGF;
                y = y * p1[j] - (1.0f - p1[j]) * BIGF;
                if (m > c)     x -= BIGF;
                if (m > c + 1) y -= BIGF;
                __stcs((float2*)(out + orow + c), make_float2(x * 0.125f, y * 0.125f));
            }
        }
    }
}

// ---------------------------------------------------------------------------
extern "C" void kernel_launch(void* const* d_in, const int* in_sizes, int n_in,
                              void* d_out, int out_size)
{
    const float* lhs    = (const float*)d_in[0];
    const float* cls    = (const float*)d_in[1];
    const float* h0     = (const float*)d_in[2];
    const float* mask   = (const float*)d_in[3];
    const float* w_ih_f = (const float*)d_in[4];
    const float* w_hh_f = (const float*)d_in[5];
    const float* b_ih_f = (const float*)d_in[6];
    const float* b_hh_f = (const float*)d_in[7];
    const float* w_ih_b = (const float*)d_in[8];
    const float* w_hh_b = (const float*)d_in[9];
    const float* b_ih_b = (const float*)d_in[10];
    const float* b_hh_b = (const float*)d_in[11];
    const float* dw     = (const float*)d_in[12];
    const float* db     = (const float*)d_in[13];
    float* out = (float*)d_out;

    cudaFuncSetAttribute(dense_mma_kernel, cudaFuncAttributeMaxDynamicSharedMemorySize, DSMEM_DENSE);
    cudaFuncSetAttribute(logits_kernel,    cudaFuncAttributeMaxDynamicSharedMemorySize, DSMEM_LOG);

    rope_tab_kernel<<<64, 256>>>();
    conv_w_kernel<<<(NOUT * KDIM / 4) / 256, 256>>>(dw);
    gru_kernel<<<dim3(12, 2), 256>>>(cls, h0, w_ih_f, w_hh_f, b_ih_f, b_hh_f,
                                     w_ih_b, w_hh_b, b_ih_b, b_hh_b);
    build_hidden_kernel<<<(MDIM * KDIM / 4) / 256, 256>>>(lhs);

    dense_mma_kernel<<<dim3(ENT, MDIM / 128), 256, DSMEM_DENSE>>>(db);

    logits_kernel<<<dim3(16, ENT, BB), 256, DSMEM_LOG>>>(mask, out);
}